// round 9
// baseline (speedup 1.0000x reference)
#include <cuda_runtime.h>

// Problem dims
#define TT 512
#define BB 64
#define HH 1024
#define GG 4096            // 4*H
#define BH (BB*HH)
#define KT 64              // K tile
#define NTILES 32          // 2048 / 64
#define NSTAGE 3
#define NTILE 32           // preact columns per CTA (8 js x 4 gates)
#define NJ 8
#define AW 68              // padded smem row stride (floats)
#define THREADS 256
#define GRID 128           // <= 148 SMs -> whole grid resident in wave 1

// ---- static device scratch (no runtime allocation) ----
__device__ float g_xr[(size_t)TT * BH];          // tf32-rounded x          (134 MB)
__device__ float g_hr0[(size_t)(TT + 1) * BH];   // rounded layer-0 h hist  (134 MB) slot0 = h0[0]
__device__ float g_hr1[(size_t)(TT + 1) * BH];   // rounded layer-1 h hist  (134 MB) slot0 = h0[1]
__device__ float g_wr[2][2][(size_t)GG * HH];    // rounded [layer][Wi|Wh]  (67 MB)
__device__ float g_c[BH];                        // cell state (CTA-private columns)
__device__ float g_hlast0[BH];                   // exact layer-0 h at t=T-1
__device__ unsigned g_bar;                       // grid barrier counter (reset in-kernel)

__device__ __forceinline__ float tf32r(float f) {
    unsigned u;
    asm("cvt.rna.tf32.f32 %0, %1;" : "=r"(u) : "f"(f));
    return __uint_as_float(u);
}

__device__ __forceinline__ void cp16(float* dst, const float* src) {
    unsigned s = (unsigned)__cvta_generic_to_shared(dst);
    asm volatile("cp.async.cg.shared.global [%0], [%1], 16;\n" :: "r"(s), "l"(src));
}

__device__ __forceinline__ void mma_tf32(float* d,
                                         unsigned a0, unsigned a1, unsigned a2, unsigned a3,
                                         unsigned b0, unsigned b1) {
    asm volatile(
        "mma.sync.aligned.m16n8k8.row.col.f32.tf32.tf32.f32 "
        "{%0,%1,%2,%3}, {%4,%5,%6,%7}, {%8,%9}, {%0,%1,%2,%3};\n"
        : "+f"(d[0]), "+f"(d[1]), "+f"(d[2]), "+f"(d[3])
        : "r"(a0), "r"(a1), "r"(a2), "r"(a3), "r"(b0), "r"(b1));
}

__global__ void __launch_bounds__(THREADS) lstm_persist(
    const float* __restrict__ x,   // [T,B,H]
    const float* __restrict__ h0,  // [L,B,H]
    const float* __restrict__ c0,  // [L,B,H]
    const float* __restrict__ Wi,  // [L,4H,H]
    const float* __restrict__ bi,  // [L,4H]
    const float* __restrict__ Wh,  // [L,4H,H]
    const float* __restrict__ bh,  // [L,4H]
    float* __restrict__ out,       // [T,B,H] layer-1 h history
    float* __restrict__ tail)      // [4,B,H]
{
    extern __shared__ float smem[];
    const int tid = threadIdx.x;
    const int bid = blockIdx.x;
    unsigned bphase = 0;  // arrive rounds issued by this CTA (lockstep across grid)

    // --- grid barrier (cooperative-groups pattern: one arriver/spinner per CTA) ---
    auto g_arrive = [&]() {
        __syncthreads();                 // all CTA writes done + smem reuse fence
        if (tid == 0) {
            __threadfence();             // make them gpu-visible
            atomicAdd(&g_bar, 1u);
        }
        bphase++;
    };
    auto g_wait = [&]() {
        if (tid == 0) {
            const unsigned tgt = bphase * GRID;
            while (*(volatile unsigned*)&g_bar < tgt) __nanosleep(32);
            __threadfence();
        }
        __syncthreads();
    };

    // =================== Prologue: pre-round W, x, h0 to tf32 ===================
    {
        const size_t gstride = (size_t)GRID * THREADS;
        const size_t g0 = (size_t)bid * THREADS + tid;

        const float4* sx = (const float4*)x;
        float4* dx = (float4*)g_xr;
        for (size_t i = g0; i < (size_t)TT * BH / 4; i += gstride) {
            float4 v = sx[i];
            v.x = tf32r(v.x); v.y = tf32r(v.y); v.z = tf32r(v.z); v.w = tf32r(v.w);
            dx[i] = v;
        }
        for (int l = 0; l < 2; l++) {
            const float4* si = (const float4*)(Wi + (size_t)l * GG * HH);
            const float4* sh = (const float4*)(Wh + (size_t)l * GG * HH);
            float4* di = (float4*)g_wr[l][0];
            float4* dh = (float4*)g_wr[l][1];
            for (size_t i = g0; i < (size_t)GG * HH / 4; i += gstride) {
                float4 v = si[i];
                v.x = tf32r(v.x); v.y = tf32r(v.y); v.z = tf32r(v.z); v.w = tf32r(v.w);
                di[i] = v;
                float4 w = sh[i];
                w.x = tf32r(w.x); w.y = tf32r(w.y); w.z = tf32r(w.z); w.w = tf32r(w.w);
                dh[i] = w;
            }
        }
        const float4* s0 = (const float4*)h0;
        float4* dh0 = (float4*)g_hr0;
        float4* dh1 = (float4*)g_hr1;
        for (size_t i = g0; i < (size_t)BH / 4; i += gstride) {
            float4 v = s0[i];
            v.x = tf32r(v.x); v.y = tf32r(v.y); v.z = tf32r(v.z); v.w = tf32r(v.w);
            dh0[i] = v;
            float4 w = s0[i + BH / 4];
            w.x = tf32r(w.x); w.y = tf32r(w.y); w.z = tf32r(w.z); w.w = tf32r(w.w);
            dh1[i] = w;
        }
    }
    g_arrive();
    g_wait();

    // =================== Recurrence ===================
    const int jb   = bid * NJ;
    const int lane = tid & 31;
    const int wid  = tid >> 5;
    const int gid  = lane >> 2;
    const int tI   = lane & 3;
    const int mr   = (wid & 3) << 4;
    const int nc   = (wid >> 2) << 4;

    float* As = smem;                        // [NSTAGE][BB][AW]
    float* Ws = smem + NSTAGE * (BB * AW);   // [NSTAGE][NTILE][AW]

    for (int l = 0; l < 2; l++) {
        const float* Wir  = g_wr[l][0];
        const float* Whr  = g_wr[l][1];
        const float* biL  = bi + (size_t)l * GG;
        const float* bhL  = bh + (size_t)l * GG;
        const float* xbase = l ? (g_hr0 + BH) : g_xr;   // layer1 input = layer0 h_t (rounded)
        float* hrA = l ? g_hr1 : g_hr0;

        for (int t = 0; t < TT; t++) {
            const float* xpart  = xbase + (size_t)t * BH;
            const float* hprev  = hrA + (size_t)t * BH;        // slot t = rounded h_{t-1}
            const float* cprev  = (t == 0) ? (c0 + (size_t)l * BH) : g_c;
            float* hr_out       = hrA + (size_t)(t + 1) * BH;
            float* hex          = (l == 1) ? (out + (size_t)t * BH)
                                           : ((t == TT - 1) ? g_hlast0 : (float*)0);

            float d0[4] = {0.f, 0.f, 0.f, 0.f};
            float d1[4] = {0.f, 0.f, 0.f, 0.f};

            auto load_tile = [&](int stage, int tile) {
                const int kt = tile * KT;
                const float* Ab = (kt < HH) ? (xpart + kt) : (hprev + (kt - HH));
                const float* Wb = (kt < HH) ? (Wir + kt) : (Whr + (kt - HH));
                float* Ad = As + stage * (BB * AW);
                float* Wd = Ws + stage * (NTILE * AW);
                #pragma unroll
                for (int j = 0; j < 4; j++) {          // A: 64x64 f32 = 1024 float4
                    int f4  = tid + j * THREADS;
                    int row = f4 >> 4;
                    int c4  = f4 & 15;
                    cp16(Ad + row * AW + c4 * 4, Ab + (size_t)row * HH + c4 * 4);
                }
                #pragma unroll
                for (int j = 0; j < 2; j++) {          // W: 32x64 f32 = 512 float4
                    int f4 = tid + j * THREADS;
                    int s  = f4 >> 4;
                    int c4 = f4 & 15;
                    int grow = ((s >> 3) * HH) + jb + (s & 7);
                    cp16(Wd + s * AW + c4 * 4, Wb + (size_t)grow * HH + c4 * 4);
                }
            };

            // prologue: tiles 0,1 (x-part — no dependency on h_{t-1})
            load_tile(0, 0);
            asm volatile("cp.async.commit_group;\n");
            load_tile(1, 1);
            asm volatile("cp.async.commit_group;\n");

            for (int tt = 0; tt < NTILES; tt++) {
                asm volatile("cp.async.wait_group 1;\n");
                __syncthreads();
                if (tt == 14) g_wait();    // lazy: needed only before first h-tile (16) load
                if (tt + 2 < NTILES) load_tile((tt + 2) % NSTAGE, tt + 2);
                asm volatile("cp.async.commit_group;\n");

                const float* Ac  = As + (tt % NSTAGE) * (BB * AW);
                const float* Wc  = Ws + (tt % NSTAGE) * (NTILE * AW);
                const float* Ar0 = Ac + (mr + gid) * AW + tI;
                const float* Ar1 = Ac + (mr + gid + 8) * AW + tI;
                const float* Wr0 = Wc + (nc + gid) * AW + tI;
                const float* Wr1 = Wc + (nc + 8 + gid) * AW + tI;

                #pragma unroll
                for (int k8 = 0; k8 < KT / 8; k8++) {
                    const int k0 = k8 * 8;
                    unsigned a0 = __float_as_uint(Ar0[k0]);
                    unsigned a1 = __float_as_uint(Ar1[k0]);
                    unsigned a2 = __float_as_uint(Ar0[k0 + 4]);
                    unsigned a3 = __float_as_uint(Ar1[k0 + 4]);
                    unsigned b0 = __float_as_uint(Wr0[k0]);
                    unsigned b1 = __float_as_uint(Wr0[k0 + 4]);
                    mma_tf32(d0, a0, a1, a2, a3, b0, b1);
                    unsigned c0u = __float_as_uint(Wr1[k0]);
                    unsigned c1u = __float_as_uint(Wr1[k0 + 4]);
                    mma_tf32(d1, a0, a1, a2, a3, c0u, c1u);
                }
            }

            asm volatile("cp.async.wait_group 0;\n");
            __syncthreads();

            // stage preact [64][32] into smem (stride 33)
            float* P = smem;
            {
                int col0 = nc + tI * 2;
                P[(mr + gid) * 33 + col0]         = d0[0];
                P[(mr + gid) * 33 + col0 + 1]     = d0[1];
                P[(mr + gid + 8) * 33 + col0]     = d0[2];
                P[(mr + gid + 8) * 33 + col0 + 1] = d0[3];
                int col1 = nc + 8 + tI * 2;
                P[(mr + gid) * 33 + col1]         = d1[0];
                P[(mr + gid) * 33 + col1 + 1]     = d1[1];
                P[(mr + gid + 8) * 33 + col1]     = d1[2];
                P[(mr + gid + 8) * 33 + col1 + 1] = d1[3];
            }
            __syncthreads();

            // elementwise LSTM for this CTA's 8 columns x 64 rows (fp32 exact)
            for (int cell = tid; cell < BB * NJ; cell += THREADS) {
                int b = cell >> 3;
                int r = cell & 7;
                int j = jb + r;
                size_t idx = (size_t)b * HH + j;
                float p0 = P[b * 33 + r]      + biL[j]          + bhL[j];
                float p1 = P[b * 33 + 8 + r]  + biL[HH + j]     + bhL[HH + j];
                float p2 = P[b * 33 + 16 + r] + biL[2 * HH + j] + bhL[2 * HH + j];
                float p3 = P[b * 33 + 24 + r] + biL[3 * HH + j] + bhL[3 * HH + j];
                float ig = 1.f / (1.f + expf(-p0));
                float fg = 1.f / (1.f + expf(-p1));
                float gg = tanhf(p2);
                float og = 1.f / (1.f + expf(-p3));
                float cc = cprev[idx] * fg + ig * gg;
                g_c[idx] = cc;
                float hh = og * tanhf(cc);
                hr_out[idx] = tf32r(hh);            // rounded shadow for mma consumers
                if (hex) hex[idx] = hh;             // exact h where required
            }

            g_arrive();   // includes __syncthreads -> also fences smem reuse
        }
        g_wait();         // layer boundary: next layer's x-tiles read this layer's h
    }

    // =================== Finalize tail ===================
    // output_hs = [h0_last, h1_last]; output_cs replicated (reference bug)
    const float* h1l = out + (size_t)(TT - 1) * BH;
    for (int i = bid * THREADS + tid; i < BH; i += GRID * THREADS) {
        float a = g_hlast0[i];
        float b = h1l[i];
        tail[i]          = a;
        tail[BH + i]     = b;
        tail[2 * BH + i] = a;
        tail[3 * BH + i] = b;
    }

    // reset the barrier counter for the next graph replay (deterministic)
    g_arrive();
    g_wait();
    if (bid == 0 && tid == 0) g_bar = 0;
}

extern "C" void kernel_launch(void* const* d_in, const int* in_sizes, int n_in,
                              void* d_out, int out_size) {
    const float* x  = (const float*)d_in[0];
    const float* h0 = (const float*)d_in[1];
    const float* c0 = (const float*)d_in[2];
    const float* Wi = (const float*)d_in[3];
    const float* bi = (const float*)d_in[4];
    const float* Wh = (const float*)d_in[5];
    const float* bh = (const float*)d_in[6];

    float* out  = (float*)d_out;                  // hs [T,B,H]
    float* tail = out + (size_t)TT * BH;          // [4,B,H]

    const size_t smemSz = (size_t)(NSTAGE * BB * AW + NSTAGE * NTILE * AW) * sizeof(float); // 78336
    cudaFuncSetAttribute(lstm_persist, cudaFuncAttributeMaxDynamicSharedMemorySize, (int)smemSz);

    lstm_persist<<<GRID, THREADS, smemSz>>>(x, h0, c0, Wi, bi, Wh, bh, out, tail);
}

// round 10
// speedup vs baseline: 1.4160x; 1.4160x over previous
#include <cuda_runtime.h>

// Problem dims
#define TT 512
#define BB 64
#define HH 1024
#define GG 4096            // 4*H
#define BH (BB*HH)
#define KT 64              // K tile (columns)
#define NTILES 32          // 2048 / 64
#define NTILE 32           // preact columns per CTA (8 js x 4 gates)
#define NJ 8
#define AW 68              // padded smem row stride (floats), 272B = 17*16
#define THREADS 256
#define GRID 128           // <= 148 SMs: whole grid resident in wave 1
#define KGROUPS 4          // warp-pair K groups
#define TPG 8              // K tiles per group (4 x-part + 4 h-part)
#define STAGEF ((64 + 32) * AW)   // floats per pipeline stage (A 64 rows + W 32 rows)

// ---- static device scratch (no runtime allocation) ----
__device__ float g_xr[(size_t)TT * BH];          // tf32-rounded x
__device__ float g_hr0[(size_t)(TT + 1) * BH];   // rounded layer-0 h history (slot0 = h0[0])
__device__ float g_hr1[(size_t)(TT + 1) * BH];   // rounded layer-1 h history (slot0 = h0[1])
__device__ float g_wr[2][2][(size_t)GG * HH];    // rounded [layer][Wi|Wh]
__device__ float g_c[BH];                        // cell state (CTA-private columns)
__device__ float g_hlast0[BH];                   // exact layer-0 h at t=T-1
__device__ unsigned g_bar;                       // grid barrier counter
__device__ unsigned g_done;                      // exit counter for replay-safe reset

__device__ __forceinline__ float tf32r(float f) {
    unsigned u;
    asm("cvt.rna.tf32.f32 %0, %1;" : "=r"(u) : "f"(f));
    return __uint_as_float(u);
}

__device__ __forceinline__ void cp16(float* dst, const float* src) {
    unsigned s = (unsigned)__cvta_generic_to_shared(dst);
    asm volatile("cp.async.cg.shared.global [%0], [%1], 16;\n" :: "r"(s), "l"(src));
}

__device__ __forceinline__ void mma_tf32(float* d,
                                         unsigned a0, unsigned a1, unsigned a2, unsigned a3,
                                         unsigned b0, unsigned b1) {
    asm volatile(
        "mma.sync.aligned.m16n8k8.row.col.f32.tf32.tf32.f32 "
        "{%0,%1,%2,%3}, {%4,%5,%6,%7}, {%8,%9}, {%0,%1,%2,%3};\n"
        : "+f"(d[0]), "+f"(d[1]), "+f"(d[2]), "+f"(d[3])
        : "r"(a0), "r"(a1), "r"(a2), "r"(a3), "r"(b0), "r"(b1));
}

__device__ __forceinline__ float sigm(float x) { return 1.f / (1.f + __expf(-x)); }
__device__ __forceinline__ float tanh_f(float x) { return 2.f / (1.f + __expf(-2.f * x)) - 1.f; }

__global__ void __launch_bounds__(THREADS, 1) lstm_persist(
    const float* __restrict__ x,   // [T,B,H]
    const float* __restrict__ h0,  // [L,B,H]
    const float* __restrict__ c0,  // [L,B,H]
    const float* __restrict__ Wi,  // [L,4H,H]
    const float* __restrict__ bi,  // [L,4H]
    const float* __restrict__ Wh,  // [L,4H,H]
    const float* __restrict__ bh,  // [L,4H]
    float* __restrict__ out,       // [T,B,H] layer-1 h history
    float* __restrict__ tail)      // [4,B,H]
{
    extern __shared__ float smem[];
    const int tid  = threadIdx.x;
    const int bid  = blockIdx.x;
    const int wid  = tid >> 5;
    const int lane = tid & 31;
    const int grp  = wid >> 1;     // K group 0..3
    const int wg   = wid & 1;      // warp within group: M half
    const int tg   = tid & 63;     // thread within group
    const int gid  = lane >> 2;    // 0..7
    const int tI   = lane & 3;     // 0..3
    const int jb   = bid * NJ;
    unsigned bphase = 0;           // arrives issued by this CTA (grid-lockstep)

    auto barg = [&]() { asm volatile("bar.sync %0, 64;" :: "r"(grp + 1) : "memory"); };

    auto g_arrive = [&]() {
        __syncthreads();
        if (tid == 0) { __threadfence(); atomicAdd(&g_bar, 1u); }
        bphase++;
    };
    auto g_wait_full = [&]() {     // full-CTA wait (prologue / layer boundary)
        if (tid == 0) {
            const unsigned tgt = bphase * GRID;
            while (*(volatile unsigned*)&g_bar < tgt) __nanosleep(64);
            __threadfence();
        }
        __syncthreads();
    };

    // =================== Prologue: pre-round W, x, h0 to tf32 ===================
    {
        const size_t gstride = (size_t)GRID * THREADS;
        const size_t g0 = (size_t)bid * THREADS + tid;

        const float4* sx = (const float4*)x;
        float4* dx = (float4*)g_xr;
        for (size_t i = g0; i < (size_t)TT * BH / 4; i += gstride) {
            float4 v = sx[i];
            v.x = tf32r(v.x); v.y = tf32r(v.y); v.z = tf32r(v.z); v.w = tf32r(v.w);
            dx[i] = v;
        }
        for (int l = 0; l < 2; l++) {
            const float4* si = (const float4*)(Wi + (size_t)l * GG * HH);
            const float4* sh = (const float4*)(Wh + (size_t)l * GG * HH);
            float4* di = (float4*)g_wr[l][0];
            float4* dh = (float4*)g_wr[l][1];
            for (size_t i = g0; i < (size_t)GG * HH / 4; i += gstride) {
                float4 v = si[i];
                v.x = tf32r(v.x); v.y = tf32r(v.y); v.z = tf32r(v.z); v.w = tf32r(v.w);
                di[i] = v;
                float4 w = sh[i];
                w.x = tf32r(w.x); w.y = tf32r(w.y); w.z = tf32r(w.z); w.w = tf32r(w.w);
                dh[i] = w;
            }
        }
        const float4* s0 = (const float4*)h0;
        float4* dh0 = (float4*)g_hr0;
        float4* dh1 = (float4*)g_hr1;
        for (size_t i = g0; i < (size_t)BH / 4; i += gstride) {
            float4 v = s0[i];
            v.x = tf32r(v.x); v.y = tf32r(v.y); v.z = tf32r(v.z); v.w = tf32r(v.w);
            dh0[i] = v;
            float4 w = s0[i + BH / 4];
            w.x = tf32r(w.x); w.y = tf32r(w.y); w.z = tf32r(w.z); w.w = tf32r(w.w);
            dh1[i] = w;
        }
    }
    g_arrive();
    g_wait_full();

    // =================== Recurrence ===================
    for (int l = 0; l < 2; l++) {
        const float* Wir = g_wr[l][0];
        const float* Whr = g_wr[l][1];
        const float* biL = bi + (size_t)l * GG;
        const float* bhL = bh + (size_t)l * GG;
        const float* xbase = l ? (g_hr0 + BH) : g_xr;
        float* hrA = l ? g_hr1 : g_hr0;

        // per-layer bias sums for this thread's 2 cells
        float bsum[2][4];
        #pragma unroll
        for (int c = 0; c < 2; c++) {
            int cell = tid + c * 256;
            int j = jb + (cell & 7);
            #pragma unroll
            for (int q = 0; q < 4; q++) bsum[c][q] = biL[q * HH + j] + bhL[q * HH + j];
        }

        for (int t = 0; t < TT; t++) {
            const float* xpart = xbase + (size_t)t * BH;
            const float* hprev = hrA + (size_t)t * BH;
            const float* cprev = (t == 0) ? (c0 + (size_t)l * BH) : g_c;
            float* hr_out      = hrA + (size_t)(t + 1) * BH;
            float* hex         = (l == 1) ? (out + (size_t)t * BH)
                                          : ((t == TT - 1) ? g_hlast0 : (float*)0);

            float dd[32];
            #pragma unroll
            for (int i = 0; i < 32; i++) dd[i] = 0.f;

            // group g handles tiles {g*4..g*4+3} (x-part) then {16+g*4..16+g*4+3} (h-part)
            auto tidx = [&](int i) { return (i < 4) ? (grp * 4 + i) : (16 + grp * 4 + (i - 4)); };

            auto load_tile = [&](int stage, int tile) {
                const int kt = tile * KT;
                const float* Ab = (kt < HH) ? (xpart + kt) : (hprev + (kt - HH));
                const float* Wb = (kt < HH) ? (Wir + kt) : (Whr + (kt - HH));
                float* Ad = smem + (size_t)(grp * 2 + stage) * STAGEF;
                float* Wd = Ad + 64 * AW;
                #pragma unroll
                for (int j = 0; j < 16; j++) {        // A: 64x64 f32 = 1024 float4 / 64 thr
                    int f4  = tg + j * 64;
                    int row = f4 >> 4;
                    int c4  = f4 & 15;
                    cp16(Ad + row * AW + c4 * 4, Ab + (size_t)row * HH + c4 * 4);
                }
                #pragma unroll
                for (int j = 0; j < 8; j++) {         // W: 32x64 f32 = 512 float4 / 64 thr
                    int f4 = tg + j * 64;
                    int s  = f4 >> 4;
                    int c4 = f4 & 15;
                    int grow = ((s >> 3) * HH) + jb + (s & 7);
                    cp16(Wd + s * AW + c4 * 4, Wb + (size_t)grow * HH + c4 * 4);
                }
            };

            auto compute = [&](int st) {
                const float* Ac  = smem + (size_t)(grp * 2 + st) * STAGEF;
                const float* Wc  = Ac + 64 * AW;
                const float* Am0 = Ac + (wg * 32 + gid) * AW + tI;
                const float* Am1 = Am0 + 16 * AW;
                const float* Wn  = Wc + gid * AW + tI;
                #pragma unroll
                for (int k8 = 0; k8 < 8; k8++) {
                    const int k0 = k8 * 8;
                    unsigned a00 = __float_as_uint(Am0[k0]);
                    unsigned a01 = __float_as_uint(Am0[8 * AW + k0]);
                    unsigned a02 = __float_as_uint(Am0[k0 + 4]);
                    unsigned a03 = __float_as_uint(Am0[8 * AW + k0 + 4]);
                    unsigned a10 = __float_as_uint(Am1[k0]);
                    unsigned a11 = __float_as_uint(Am1[8 * AW + k0]);
                    unsigned a12 = __float_as_uint(Am1[k0 + 4]);
                    unsigned a13 = __float_as_uint(Am1[8 * AW + k0 + 4]);
                    #pragma unroll
                    for (int n = 0; n < 4; n++) {
                        unsigned b0 = __float_as_uint(Wn[n * 8 * AW + k0]);
                        unsigned b1 = __float_as_uint(Wn[n * 8 * AW + k0 + 4]);
                        mma_tf32(dd + n * 4,      a00, a01, a02, a03, b0, b1);
                        mma_tf32(dd + 16 + n * 4, a10, a11, a12, a13, b0, b1);
                    }
                }
            };

            // 2-stage group-local pipeline
            load_tile(0, tidx(0));
            asm volatile("cp.async.commit_group;\n");
            load_tile(1, tidx(1));
            asm volatile("cp.async.commit_group;\n");

            #pragma unroll 1
            for (int i = 0; i < TPG; i++) {
                asm volatile("cp.async.wait_group 1;\n");
                barg();                            // both warps see the landed tile
                compute(i & 1);
                barg();                            // both warps done with this stage
                if (i == 2) {                      // just before first h-tile load
                    if (tg == 0) {
                        const unsigned tgt = bphase * GRID;
                        while (*(volatile unsigned*)&g_bar < tgt) __nanosleep(64);
                        __threadfence();
                    }
                    barg();
                }
                if (i < TPG - 2) load_tile(i & 1, tidx(i + 2));
                asm volatile("cp.async.commit_group;\n");
            }
            asm volatile("cp.async.wait_group 0;\n");
            __syncthreads();

            // write this group's partial [64][32] (stride 33) into P_grp
            {
                float* Pg = smem + grp * (64 * 33);
                #pragma unroll
                for (int m = 0; m < 2; m++) {
                    int rb = wg * 32 + m * 16 + gid;
                    #pragma unroll
                    for (int n = 0; n < 4; n++) {
                        const float* d4 = dd + m * 16 + n * 4;
                        int cb = n * 8 + tI * 2;
                        Pg[rb * 33 + cb]           = d4[0];
                        Pg[rb * 33 + cb + 1]       = d4[1];
                        Pg[(rb + 8) * 33 + cb]     = d4[2];
                        Pg[(rb + 8) * 33 + cb + 1] = d4[3];
                    }
                }
            }
            __syncthreads();

            // elementwise LSTM: sum 4 group partials + bias, fp32 exact
            #pragma unroll
            for (int c = 0; c < 2; c++) {
                int cell = tid + c * 256;
                int b = cell >> 3;
                int r = cell & 7;
                int j = jb + r;
                size_t idx = (size_t)b * HH + j;
                float p0 = bsum[c][0], p1 = bsum[c][1], p2 = bsum[c][2], p3 = bsum[c][3];
                #pragma unroll
                for (int g = 0; g < KGROUPS; g++) {
                    const float* Pg = smem + g * (64 * 33);
                    p0 += Pg[b * 33 + r];
                    p1 += Pg[b * 33 + 8 + r];
                    p2 += Pg[b * 33 + 16 + r];
                    p3 += Pg[b * 33 + 24 + r];
                }
                float ig = sigm(p0);
                float fg = sigm(p1);
                float gg = tanh_f(p2);
                float og = sigm(p3);
                float cc = cprev[idx] * fg + ig * gg;
                g_c[idx] = cc;
                float hh = og * tanh_f(cc);
                hr_out[idx] = tf32r(hh);
                if (hex) hex[idx] = hh;
            }

            g_arrive();   // syncthreads inside also fences smem reuse
        }
        g_wait_full();    // next layer's x-tiles read this layer's full h history
    }

    // =================== Finalize tail ===================
    const float* h1l = out + (size_t)(TT - 1) * BH;
    for (int i = bid * THREADS + tid; i < BH; i += GRID * THREADS) {
        float a = g_hlast0[i];
        float b = h1l[i];
        tail[i]          = a;
        tail[BH + i]     = b;
        tail[2 * BH + i] = a;
        tail[3 * BH + i] = b;
    }

    // replay-safe barrier reset: last exiting CTA resets both counters
    g_arrive();
    g_wait_full();
    if (tid == 0) {
        unsigned old = atomicAdd(&g_done, 1u);
        if (old == GRID - 1) {
            g_bar = 0;
            g_done = 0;
            __threadfence();
        }
    }
}

extern "C" void kernel_launch(void* const* d_in, const int* in_sizes, int n_in,
                              void* d_out, int out_size) {
    const float* x  = (const float*)d_in[0];
    const float* h0 = (const float*)d_in[1];
    const float* c0 = (const float*)d_in[2];
    const float* Wi = (const float*)d_in[3];
    const float* bi = (const float*)d_in[4];
    const float* Wh = (const float*)d_in[5];
    const float* bh = (const float*)d_in[6];

    float* out  = (float*)d_out;               // hs [T,B,H]
    float* tail = out + (size_t)TT * BH;       // [4,B,H]

    const size_t smemSz = (size_t)(2 * KGROUPS) * STAGEF * sizeof(float);   // 208,896 B
    cudaFuncSetAttribute(lstm_persist, cudaFuncAttributeMaxDynamicSharedMemorySize, (int)smemSz);

    lstm_persist<<<GRID, THREADS, smemSz>>>(x, h0, c0, Wi, bi, Wh, bh, out, tail);
}

// round 14
// speedup vs baseline: 2.2916x; 1.6184x over previous
#include <cuda_runtime.h>

// Problem dims
#define TT 512
#define BB 64
#define HH 1024
#define GG 4096
#define BH (BB*HH)
#define THREADS 256
#define GRID 128          // <= 148 SMs: whole grid resident in wave 1
#define KGROUPS 4         // warp-pair K groups
#define TPG 8             // tiles per group (4 x-part + 4 h-part)
#define NJ 8              // h-columns per CTA
#define NT_A 32           // 64-wide K tiles per step matrix (K = 2048)
#define ATILE_F 4096      // floats per packed A tile (64 rows x 64 k)
#define WTILE_F 2048      // floats per packed W tile (32 cols x 64 k)
#define STAGEF (ATILE_F + WTILE_F)   // 6144 floats = 24 KB per stage

// ---- static device scratch (no runtime allocation) ----
// Packed step-A matrices: [t][tile 32][fragment-packed 4096]
__device__ float g_A0[(size_t)TT * NT_A * ATILE_F];   // layer-0 (268 MB)
__device__ float g_A1[(size_t)TT * NT_A * ATILE_F];   // layer-1 (268 MB)
// Packed W: [layer][cta 128][tile 32][fragment-packed 2048]  (67 MB)
__device__ float g_wp[2][(size_t)GRID * NT_A * WTILE_F];
__device__ float g_c[BH];         // cell state (CTA-private columns)
__device__ float g_hlast0[BH];    // exact layer-0 h at t = T-1
__device__ unsigned g_bar, g_done;

__device__ __forceinline__ float tf32r(float f) {
    unsigned u;
    asm("cvt.rna.tf32.f32 %0, %1;" : "=r"(u) : "f"(f));
    return __uint_as_float(u);
}

__device__ __forceinline__ void cp16(float* dst, const float* src) {
    unsigned s = (unsigned)__cvta_generic_to_shared(dst);
    asm volatile("cp.async.cg.shared.global [%0], [%1], 16;\n" :: "r"(s), "l"(src));
}

__device__ __forceinline__ void mma_tf32(float* d,
                                         unsigned a0, unsigned a1, unsigned a2, unsigned a3,
                                         unsigned b0, unsigned b1) {
    asm volatile(
        "mma.sync.aligned.m16n8k8.row.col.f32.tf32.tf32.f32 "
        "{%0,%1,%2,%3}, {%4,%5,%6,%7}, {%8,%9}, {%0,%1,%2,%3};\n"
        : "+f"(d[0]), "+f"(d[1]), "+f"(d[2]), "+f"(d[3])
        : "r"(a0), "r"(a1), "r"(a2), "r"(a3), "r"(b0), "r"(b1));
}

__device__ __forceinline__ float sigm(float x) { return 1.f / (1.f + __expf(-x)); }
__device__ __forceinline__ float tanh_f(float x) { return 2.f / (1.f + __expf(-2.f * x)) - 1.f; }

// Packed offset (floats) of A element (b, kg) within one step matrix.
// Fragment map (mma.m16n8k8 A): lane=(r&7)*4+(c&3), reg=(r>>3)+2*(c>>2)
__device__ __forceinline__ int packedOff(int b, int kg) {
    int tile = kg >> 6, kl = kg & 63;
    int mb = b >> 4, r = b & 15, k8 = kl >> 3, c = kl & 7;
    int lane = (r & 7) * 4 + (c & 3);
    int reg  = (r >> 3) + 2 * (c >> 2);
    return tile * ATILE_F + ((mb * 8 + k8) * 32 + lane) * 4 + reg;
}

__global__ void __launch_bounds__(THREADS, 1) lstm_persist(
    const float* __restrict__ x,   // [T,B,H]
    const float* __restrict__ h0,  // [L,B,H]
    const float* __restrict__ c0,  // [L,B,H]
    const float* __restrict__ Wi,  // [L,4H,H]
    const float* __restrict__ bi,  // [L,4H]
    const float* __restrict__ Wh,  // [L,4H,H]
    const float* __restrict__ bh,  // [L,4H]
    float* __restrict__ out,       // [T,B,H]
    float* __restrict__ tail)      // [4,B,H]
{
    extern __shared__ float smem[];
    const int tid  = threadIdx.x;
    const int bid  = blockIdx.x;
    const int wid  = tid >> 5;
    const int lane = tid & 31;
    const int grp  = wid >> 1;     // K group 0..3
    const int wg   = wid & 1;      // warp within group (M half)
    const int tg   = tid & 63;     // thread within group
    const int gid  = lane >> 2;
    const int tI   = lane & 3;
    const int jb   = bid * NJ;
    unsigned bphase = 0;

    auto barg = [&]() { asm volatile("bar.sync %0, 64;" :: "r"(grp + 1) : "memory"); };
    auto g_arrive = [&]() {
        __syncthreads();
        if (tid == 0) { __threadfence(); atomicAdd(&g_bar, 1u); }
        bphase++;
    };
    auto g_wait_full = [&]() {
        if (tid == 0) {
            const unsigned tgt = bphase * GRID;
            while (*(volatile unsigned*)&g_bar < tgt) __nanosleep(64);
            __threadfence();
        }
        __syncthreads();
    };

    // =================== Prologue: pack x, W, h0 (tf32-rounded, fragment order) ==========
    {
        const size_t gt = (size_t)bid * THREADS + tid;
        const size_t gs = (size_t)GRID * THREADS;

        // (1) x-part of g_A0: tiles 0..15 for every t. Dest-coalesced float4 writes.
        for (size_t i = gt; i < (size_t)TT * 16 * 1024; i += gs) {
            int t    = (int)(i >> 14);
            int rem  = (int)(i & 16383);
            int tile = rem >> 10;
            int f4   = rem & 1023;
            int mb = f4 >> 8, k8 = (f4 >> 5) & 7, ln = f4 & 31;
            float4 v;
            float* vv = (float*)&v;
            #pragma unroll
            for (int rg = 0; rg < 4; rg++) {
                int b  = mb * 16 + (rg & 1) * 8 + (ln >> 2);
                int c  = (rg >> 1) * 4 + (ln & 3);
                int kg = tile * 64 + k8 * 8 + c;
                vv[rg] = tf32r(x[(size_t)t * BH + (size_t)b * HH + kg]);
            }
            ((float4*)g_A0)[(size_t)t * (NT_A * ATILE_F / 4) + tile * (ATILE_F / 4) + f4] = v;
        }

        // (2) packed W for both layers / all CTAs / all tiles.
        {
            const size_t per = (size_t)GRID * NT_A * 512;
            for (size_t i = gt; i < 2 * per; i += gs) {
                int l = (int)(i / per);
                size_t rem = i % per;
                int cj   = (int)(rem / (NT_A * 512));
                int rem2 = (int)(rem % (NT_A * 512));
                int tile = rem2 >> 9;
                int f4   = rem2 & 511;
                int k8 = f4 >> 6, npair = (f4 >> 5) & 1, ln = f4 & 31;
                float4 v;
                float* vv = (float*)&v;
                #pragma unroll
                for (int f = 0; f < 4; f++) {
                    int n8 = npair * 2 + (f >> 1);
                    int kk = (f & 1) * 4 + (ln & 3);
                    int s  = n8 * 8 + (ln >> 2);
                    int grow = (s >> 3) * HH + cj * NJ + (s & 7);
                    int kg = tile * 64 + k8 * 8 + kk;
                    const float* Wsrc = (kg < HH) ? (Wi + (size_t)l * GG * HH)
                                                  : (Wh + (size_t)l * GG * HH);
                    vv[f] = tf32r(Wsrc[(size_t)grow * HH + (kg & (HH - 1))]);
                }
                ((float4*)g_wp)[(size_t)l * per + (size_t)cj * (NT_A * 512) + tile * 512 + f4] = v;
            }
        }

        // (3) h0 -> h-part (tiles 16..31) of step-0 matrices
        for (size_t i = gt; i < 2 * 16 * 1024; i += gs) {
            int l    = (int)(i >> 14);
            int rem  = (int)(i & 16383);
            int tile = 16 + (rem >> 10);
            int f4   = rem & 1023;
            int mb = f4 >> 8, k8 = (f4 >> 5) & 7, ln = f4 & 31;
            float4 v;
            float* vv = (float*)&v;
            #pragma unroll
            for (int rg = 0; rg < 4; rg++) {
                int b = mb * 16 + (rg & 1) * 8 + (ln >> 2);
                int c = (rg >> 1) * 4 + (ln & 3);
                int j = (tile - 16) * 64 + k8 * 8 + c;
                vv[rg] = tf32r(h0[(size_t)l * BH + (size_t)b * HH + j]);
            }
            float* dst = l ? g_A1 : g_A0;
            ((float4*)dst)[tile * (ATILE_F / 4) + f4] = v;
        }
    }
    g_arrive();
    g_wait_full();

    // =================== Recurrence ===================
    for (int l = 0; l < 2; l++) {
        const float* Wp  = g_wp[l] + (size_t)bid * NT_A * WTILE_F;
        const float* biL = bi + (size_t)l * GG;
        const float* bhL = bh + (size_t)l * GG;
        float* Abase = l ? g_A1 : g_A0;

        float bsum[2][4];
        #pragma unroll
        for (int c = 0; c < 2; c++) {
            int j = jb + ((tid + c * 256) & 7);
            #pragma unroll
            for (int q = 0; q < 4; q++) bsum[c][q] = biL[q * HH + j] + bhL[q * HH + j];
        }

        for (int t = 0; t < TT; t++) {
            const float* Astep = Abase + (size_t)t * (NT_A * ATILE_F);
            const float* cprev = (t == 0) ? (c0 + (size_t)l * BH) : g_c;

            float dd[32];
            #pragma unroll
            for (int i = 0; i < 32; i++) dd[i] = 0.f;

            auto tidx = [&](int i) { return (i < 4) ? (grp * 4 + i) : (16 + grp * 4 + (i - 4)); };

            auto load_tile = [&](int stage, int tile) {
                float* Ad = smem + (size_t)(grp * 2 + stage) * STAGEF;
                float* Wd = Ad + ATILE_F;
                const float* As = Astep + (size_t)tile * ATILE_F;
                const float* Ws = Wp + (size_t)tile * WTILE_F;
                #pragma unroll
                for (int j = 0; j < 16; j++) {          // A: 1024 float4 / 64 thr
                    int f4 = tg + j * 64;
                    cp16(Ad + f4 * 4, As + f4 * 4);
                }
                #pragma unroll
                for (int j = 0; j < 8; j++) {           // W: 512 float4 / 64 thr
                    int f4 = tg + j * 64;
                    cp16(Wd + f4 * 4, Ws + f4 * 4);
                }
            };

            auto compute = [&](int st) {
                const float4* Af = (const float4*)(smem + (size_t)(grp * 2 + st) * STAGEF);
                const float4* Wf = Af + ATILE_F / 4;
                #pragma unroll
                for (int k8 = 0; k8 < 8; k8++) {
                    float4 am0 = Af[((wg * 2 + 0) * 8 + k8) * 32 + lane];
                    float4 am1 = Af[((wg * 2 + 1) * 8 + k8) * 32 + lane];
                    float4 w0  = Wf[(k8 * 2 + 0) * 32 + lane];
                    float4 w1  = Wf[(k8 * 2 + 1) * 32 + lane];
                    unsigned a00 = __float_as_uint(am0.x), a01 = __float_as_uint(am0.y);
                    unsigned a02 = __float_as_uint(am0.z), a03 = __float_as_uint(am0.w);
                    unsigned a10 = __float_as_uint(am1.x), a11 = __float_as_uint(am1.y);
                    unsigned a12 = __float_as_uint(am1.z), a13 = __float_as_uint(am1.w);
                    unsigned b0, b1;
                    b0 = __float_as_uint(w0.x); b1 = __float_as_uint(w0.y);
                    mma_tf32(dd + 0,  a00, a01, a02, a03, b0, b1);
                    mma_tf32(dd + 16, a10, a11, a12, a13, b0, b1);
                    b0 = __float_as_uint(w0.z); b1 = __float_as_uint(w0.w);
                    mma_tf32(dd + 4,  a00, a01, a02, a03, b0, b1);
                    mma_tf32(dd + 20, a10, a11, a12, a13, b0, b1);
                    b0 = __float_as_uint(w1.x); b1 = __float_as_uint(w1.y);
                    mma_tf32(dd + 8,  a00, a01, a02, a03, b0, b1);
                    mma_tf32(dd + 24, a10, a11, a12, a13, b0, b1);
                    b0 = __float_as_uint(w1.z); b1 = __float_as_uint(w1.w);
                    mma_tf32(dd + 12, a00, a01, a02, a03, b0, b1);
                    mma_tf32(dd + 28, a10, a11, a12, a13, b0, b1);
                }
            };

            load_tile(0, tidx(0));
            asm volatile("cp.async.commit_group;\n");
            load_tile(1, tidx(1));
            asm volatile("cp.async.commit_group;\n");

            #pragma unroll 1
            for (int i = 0; i < TPG; i++) {
                asm volatile("cp.async.wait_group 1;\n");
                barg();
                compute(i & 1);
                barg();
                if (i == 2) {                 // defer grid wait until before first h-tile load
                    if (tg == 0) {
                        const unsigned tgt = bphase * GRID;
                        while (*(volatile unsigned*)&g_bar < tgt) __nanosleep(64);
                        __threadfence();
                    }
                    barg();
                }
                if (i < TPG - 2) load_tile(i & 1, tidx(i + 2));
                asm volatile("cp.async.commit_group;\n");
            }
            asm volatile("cp.async.wait_group 0;\n");
            __syncthreads();

            // group partials [64][32] (stride 33)
            {
                float* Pg = smem + grp * (64 * 33);
                #pragma unroll
                for (int m = 0; m < 2; m++) {
                    int rb = wg * 32 + m * 16 + gid;
                    #pragma unroll
                    for (int n = 0; n < 4; n++) {
                        const float* d4 = dd + m * 16 + n * 4;
                        int cb = n * 8 + tI * 2;
                        Pg[rb * 33 + cb]           = d4[0];
                        Pg[rb * 33 + cb + 1]       = d4[1];
                        Pg[(rb + 8) * 33 + cb]     = d4[2];
                        Pg[(rb + 8) * 33 + cb + 1] = d4[3];
                    }
                }
            }
            __syncthreads();

            // elementwise LSTM (fp32 exact), h written into packed layouts
            #pragma unroll
            for (int c = 0; c < 2; c++) {
                int cell = tid + c * 256;
                int b = cell >> 3;
                int r = cell & 7;
                int j = jb + r;
                size_t idx = (size_t)b * HH + j;
                float p0 = bsum[c][0], p1 = bsum[c][1], p2 = bsum[c][2], p3 = bsum[c][3];
                #pragma unroll
                for (int g = 0; g < KGROUPS; g++) {
                    const float* Pg = smem + g * (64 * 33);
                    p0 += Pg[b * 33 + r];
                    p1 += Pg[b * 33 + 8 + r];
                    p2 += Pg[b * 33 + 16 + r];
                    p3 += Pg[b * 33 + 24 + r];
                }
                float ig = sigm(p0);
                float fg = sigm(p1);
                float gg = tanh_f(p2);
                float og = sigm(p3);
                float cc = cprev[idx] * fg + ig * gg;
                g_c[idx] = cc;
                float hh = og * tanh_f(cc);
                float hr = tf32r(hh);
                if (l == 0) {
                    if (t < TT - 1)
                        g_A0[(size_t)(t + 1) * (NT_A * ATILE_F) + packedOff(b, HH + j)] = hr;
                    g_A1[(size_t)t * (NT_A * ATILE_F) + packedOff(b, j)] = hr;  // layer-1 x-part
                    if (t == TT - 1) g_hlast0[idx] = hh;
                } else {
                    if (t < TT - 1)
                        g_A1[(size_t)(t + 1) * (NT_A * ATILE_F) + packedOff(b, HH + j)] = hr;
                    out[(size_t)t * BH + idx] = hh;
                }
            }

            g_arrive();
        }
        g_wait_full();
    }

    // =================== Finalize tail ===================
    const float* h1l = out + (size_t)(TT - 1) * BH;
    for (int i = bid * THREADS + tid; i < BH; i += GRID * THREADS) {
        float a = g_hlast0[i];
        float b = h1l[i];
        tail[i]          = a;
        tail[BH + i]     = b;
        tail[2 * BH + i] = a;
        tail[3 * BH + i] = b;
    }

    // replay-safe barrier reset
    g_arrive();
    g_wait_full();
    if (tid == 0) {
        unsigned old = atomicAdd(&g_done, 1u);
        if (old == GRID - 1) {
            g_bar = 0;
            g_done = 0;
            __threadfence();
        }
    }
}

extern "C" void kernel_launch(void* const* d_in, const int* in_sizes, int n_in,
                              void* d_out, int out_size) {
    const float* x  = (const float*)d_in[0];
    const float* h0 = (const float*)d_in[1];
    const float* c0 = (const float*)d_in[2];
    const float* Wi = (const float*)d_in[3];
    const float* bi = (const float*)d_in[4];
    const float* Wh = (const float*)d_in[5];
    const float* bh = (const float*)d_in[6];

    float* out  = (float*)d_out;
    float* tail = out + (size_t)TT * BH;

    const size_t smemSz = (size_t)(2 * KGROUPS) * STAGEF * sizeof(float);   // 196,608 B
    cudaFuncSetAttribute(lstm_persist, cudaFuncAttributeMaxDynamicSharedMemorySize, (int)smemSz);

    lstm_persist<<<GRID, THREADS, smemSz>>>(x, h0, c0, Wi, bi, Wh, bh, out, tail);
}